// round 12
// baseline (speedup 1.0000x reference)
#include <cuda_runtime.h>
#include <math.h>

#define Bn 32
#define Cn 512
#define HWn 3136
#define NV4 784                       // HWn / 4
#define NROWS (Bn * Cn)               // 16384
#define ROWS_PER_BLK 16
#define BLKS_PER_BATCH (Cn / ROWS_PER_BLK)   // 32
#define NGROUPS 4
#define NBLOCKS (NGROUPS * BLKS_PER_BATCH)   // 128
#define NPASS (Bn / NGROUPS)                 // 8
#define SMEM_BYTES (ROWS_PER_BLK * HWn * 4)  // 200704 B

__device__ float g_y[NROWS];
__device__ int   g_cnt[Bn];

__global__ void init_kernel() {
    if (threadIdx.x < Bn) g_cnt[threadIdx.x] = 0;
}

// Deformable-attention scalar for (b, p). __ldcg: bypass (possibly stale) L1.
__device__ __forceinline__ float attn_for(int b, int p,
                                          const float* __restrict__ wo,
                                          const float* __restrict__ wd,
                                          const float* __restrict__ bd) {
    const float* yb = g_y + b * Cn;
    float acc = bd[0];
    #pragma unroll
    for (int k = 0; k < 3; k++) {
        float off = 0.0f;
        #pragma unroll
        for (int jj = 0; jj < 3; jj++) {
            int ii = p + jj - 1;
            float yv = (ii >= 0 && ii < Cn) ? __ldcg(&yb[ii]) : 0.0f;
            off = fmaf(wo[k * 3 + jj], yv, off);
        }
        float pos = (float)(p + k - 1) + off;
        float p0 = floorf(pos);
        float frac = pos - p0;
        int p0i = (int)p0;
        float v0 = (p0i >= 0     && p0i < Cn)     ? __ldcg(&yb[p0i])     : 0.0f;
        float v1 = (p0i + 1 >= 0 && p0i + 1 < Cn) ? __ldcg(&yb[p0i + 1]) : 0.0f;
        acc = fmaf(wd[k], fmaf(v1 - v0, frac, v0), acc);
    }
    return 1.0f / (1.0f + __expf(-acc));
}

// One block = 16 channels of one batch per pass, x rows cached in SMEM so the
// scale pass re-reads from SMEM (no LTS traffic). Per-batch atomic barrier
// between mean and scale; each 32-block group is self-contained -> no deadlock
// regardless of residency.
__global__ void __launch_bounds__(1024, 1)
dca_kernel(const float* __restrict__ x, float* __restrict__ out,
           const float* __restrict__ w_offset,
           const float* __restrict__ w_deform,
           const float* __restrict__ b_deform) {
    extern __shared__ float smem[];              // 16 rows x 3136 floats
    __shared__ float part[32];
    __shared__ float sattn[ROWS_PER_BLK];

    const int group = blockIdx.x >> 5;           // 0..3
    const int j     = blockIdx.x & 31;           // block within batch
    const int warp  = threadIdx.x >> 5;          // 0..31
    const int lane  = threadIdx.x & 31;
    const int r     = warp >> 1;                 // row within block: 0..15
    const int h     = warp & 1;                  // half of the row

    for (int pass = 0; pass < NPASS; ++pass) {
        const int b   = pass * NGROUPS + group;
        const int c   = j * ROWS_PER_BLK + r;    // channel
        const int row = b * Cn + c;
        const float4* rp  = (const float4*)(x + (size_t)row * HWn);
        float4*      srow = (float4*)(smem + r * HWn);

        // ---- phase A: stream x row -> SMEM, accumulate sum ----
        float s = 0.0f;
        #pragma unroll 4
        for (int i = h * 32 + lane; i < NV4; i += 64) {
            float4 v = __ldcs(&rp[i]);           // consumed once: evict-first
            srow[i] = v;
            s += (v.x + v.y) + (v.z + v.w);
        }
        #pragma unroll
        for (int o = 16; o > 0; o >>= 1)
            s += __shfl_down_sync(0xffffffffu, s, o);
        if (lane == 0) part[warp] = s;
        __syncthreads();
        if (h == 0 && lane == 0)
            g_y[row] = (part[2 * r] + part[2 * r + 1]) * (1.0f / (float)HWn);
        __syncthreads();                          // g_y writes done block-wide

        // ---- per-batch barrier: all 32 blocks of batch b ----
        if (threadIdx.x == 0) {
            __threadfence();                      // publish g_y
            atomicAdd(&g_cnt[b], 1);
            while (atomicAdd(&g_cnt[b], 0) < BLKS_PER_BATCH) __nanosleep(64);
            __threadfence();                      // acquire
        }
        __syncthreads();

        // ---- phase B: attn per channel, scale cached row -> out ----
        if (h == 0 && lane == 0)
            sattn[r] = attn_for(b, c, w_offset, w_deform, b_deform);
        __syncthreads();
        const float a = sattn[r];

        float4* o4 = (float4*)(out + (size_t)row * HWn);
        #pragma unroll 4
        for (int i = h * 32 + lane; i < NV4; i += 64) {
            float4 v = srow[i];
            v.x *= a; v.y *= a; v.z *= a; v.w *= a;
            o4[i] = v;
        }
        __syncthreads();                          // protect smem/sattn reuse
    }
}

extern "C" void kernel_launch(void* const* d_in, const int* in_sizes, int n_in,
                              void* d_out, int out_size) {
    const float* x        = (const float*)d_in[0];
    const float* w_offset = (const float*)d_in[1];
    const float* w_deform = (const float*)d_in[2];
    const float* b_deform = (const float*)d_in[3];
    float* out = (float*)d_out;

    cudaFuncSetAttribute(dca_kernel,
                         cudaFuncAttributeMaxDynamicSharedMemorySize, SMEM_BYTES);
    init_kernel<<<1, 32>>>();
    dca_kernel<<<NBLOCKS, 1024, SMEM_BYTES>>>(x, out, w_offset, w_deform, b_deform);
}

// round 13
// speedup vs baseline: 1.0033x; 1.0033x over previous
#include <cuda_runtime.h>
#include <math.h>

#define Bn 32
#define Cn 512
#define HWn 3136
#define NV4 784                       // HWn / 4
#define NROWS (Bn * Cn)               // 16384
#define ROWS_PER_BLK 8
#define BLKS_PER_BATCH (Cn / ROWS_PER_BLK)   // 64
#define NGROUPS 4
#define NBLOCKS (NGROUPS * BLKS_PER_BATCH)   // 256  (all co-resident: 2/SM)
#define NPASS (Bn / NGROUPS)                 // 8
#define SMEM_BYTES (ROWS_PER_BLK * HWn * 4)  // 100352 B

__device__ float g_y[NROWS];
__device__ int   g_cnt[Bn];

__global__ void init_kernel() {
    if (threadIdx.x < Bn) g_cnt[threadIdx.x] = 0;
}

// Deformable-attention scalar for (b, p). __ldcg: bypass (possibly stale) L1.
__device__ __forceinline__ float attn_for(int b, int p,
                                          const float* __restrict__ wo,
                                          const float* __restrict__ wd,
                                          const float* __restrict__ bd) {
    const float* yb = g_y + b * Cn;
    float acc = bd[0];
    #pragma unroll
    for (int k = 0; k < 3; k++) {
        float off = 0.0f;
        #pragma unroll
        for (int jj = 0; jj < 3; jj++) {
            int ii = p + jj - 1;
            float yv = (ii >= 0 && ii < Cn) ? __ldcg(&yb[ii]) : 0.0f;
            off = fmaf(wo[k * 3 + jj], yv, off);
        }
        float pos = (float)(p + k - 1) + off;
        float p0 = floorf(pos);
        float frac = pos - p0;
        int p0i = (int)p0;
        float v0 = (p0i >= 0     && p0i < Cn)     ? __ldcg(&yb[p0i])     : 0.0f;
        float v1 = (p0i + 1 >= 0 && p0i + 1 < Cn) ? __ldcg(&yb[p0i + 1]) : 0.0f;
        acc = fmaf(wd[k], fmaf(v1 - v0, frac, v0), acc);
    }
    return 1.0f / (1.0f + __expf(-acc));
}

// Persistent-ish SMEM-caching kernel. 8 rows (100KB) per block, 512 threads
// (2 warps per row). 4 batch-groups of 64 blocks progress independently, so
// read-phase and write-phase traffic from different groups/blocks overlaps
// chip-wide. All 256 blocks are co-resident (2 per SM) -> per-batch spin
// barrier is deadlock-free and spin gaps are covered by the co-resident block.
__global__ void __launch_bounds__(512)
dca_kernel(const float* __restrict__ x, float* __restrict__ out,
           const float* __restrict__ w_offset,
           const float* __restrict__ w_deform,
           const float* __restrict__ b_deform) {
    extern __shared__ float smem[];              // 8 rows x 3136 floats
    __shared__ float part[16];
    __shared__ float sattn[ROWS_PER_BLK];

    const int group = blockIdx.x >> 6;           // 0..3
    const int j     = blockIdx.x & 63;           // block within batch
    const int warp  = threadIdx.x >> 5;          // 0..15
    const int lane  = threadIdx.x & 31;
    const int r     = warp >> 1;                 // row within block: 0..7
    const int h     = warp & 1;                  // half of the row

    for (int pass = 0; pass < NPASS; ++pass) {
        const int b   = pass * NGROUPS + group;
        const int c   = j * ROWS_PER_BLK + r;    // channel
        const int row = b * Cn + c;
        const float4* rp  = (const float4*)(x + (size_t)row * HWn);
        float4*      srow = (float4*)(smem + r * HWn);

        // ---- phase A: stream x row -> SMEM, accumulate sum ----
        float s = 0.0f;
        #pragma unroll 4
        for (int i = h * 32 + lane; i < NV4; i += 64) {
            float4 v = __ldcs(&rp[i]);           // read once: evict-first
            srow[i] = v;
            s += (v.x + v.y) + (v.z + v.w);
        }
        #pragma unroll
        for (int o = 16; o > 0; o >>= 1)
            s += __shfl_down_sync(0xffffffffu, s, o);
        if (lane == 0) part[warp] = s;
        __syncthreads();
        if (h == 0 && lane == 0)
            g_y[row] = (part[2 * r] + part[2 * r + 1]) * (1.0f / (float)HWn);
        __syncthreads();

        // ---- per-batch barrier: 64 blocks of batch b ----
        if (threadIdx.x == 0) {
            __threadfence();                      // publish g_y
            atomicAdd(&g_cnt[b], 1);
            while (atomicAdd(&g_cnt[b], 0) < BLKS_PER_BATCH) __nanosleep(32);
            __threadfence();                      // acquire
        }
        __syncthreads();

        // ---- phase B: attn per channel, scale cached row -> out ----
        if (h == 0 && lane == 0)
            sattn[r] = attn_for(b, c, w_offset, w_deform, b_deform);
        __syncthreads();
        const float a = sattn[r];

        float4* o4 = (float4*)(out + (size_t)row * HWn);
        #pragma unroll 4
        for (int i = h * 32 + lane; i < NV4; i += 64) {
            float4 v = srow[i];
            v.x *= a; v.y *= a; v.z *= a; v.w *= a;
            o4[i] = v;
        }
        __syncthreads();                          // protect smem/sattn reuse
    }
}

extern "C" void kernel_launch(void* const* d_in, const int* in_sizes, int n_in,
                              void* d_out, int out_size) {
    const float* x        = (const float*)d_in[0];
    const float* w_offset = (const float*)d_in[1];
    const float* w_deform = (const float*)d_in[2];
    const float* b_deform = (const float*)d_in[3];
    float* out = (float*)d_out;

    cudaFuncSetAttribute(dca_kernel,
                         cudaFuncAttributeMaxDynamicSharedMemorySize, SMEM_BYTES);
    init_kernel<<<1, 32>>>();
    dca_kernel<<<NBLOCKS, 512, SMEM_BYTES>>>(x, out, w_offset, w_deform, b_deform);
}